// round 1
// baseline (speedup 1.0000x reference)
#include <cuda_runtime.h>
#include <math.h>

// Problem constants (fixed by the dataset)
#define F_IN   32
#define DDIM   128
#define HEADS  4
#define HD     (HEADS * DDIM)   // 512
#define RNN3   384              // 3 * RNN_H
#define CAP    330000           // >= E + 1 (E = 320000)

// Scratch (allocation-free rule: __device__ globals)
__device__ int   g_src[CAP];
__device__ int   g_cnt;
__device__ float g_h0[DDIM];
__device__ float g_xr0[HD];
__device__ float g_num[HD];
__device__ float g_den[HEADS];

// ---------------------------------------------------------------------------
// K0: init accumulators, seed self-loop edge (src=0,dst=0), compute
//     h0 = relu(nf[0] @ W_enc + b_enc) and xr0 = h0 @ W_r + b_r.
// 1 block x 512 threads.
// ---------------------------------------------------------------------------
__global__ void k_init(const float* __restrict__ nf,
                       const float* __restrict__ W_enc,
                       const float* __restrict__ b_enc,
                       const float* __restrict__ W_r,
                       const float* __restrict__ b_r) {
    __shared__ float h0[DDIM];
    int t = threadIdx.x;

    g_num[t] = 0.0f;
    if (t < HEADS) g_den[t] = 0.0f;
    if (t == 0) { g_cnt = 1; g_src[0] = 0; }  // self-loop of node 0

    if (t < DDIM) {
        float acc = b_enc[t];
        #pragma unroll
        for (int k = 0; k < F_IN; k++)
            acc += nf[k] * W_enc[k * DDIM + t];
        acc = fmaxf(acc, 0.0f);
        h0[t] = acc;
        g_h0[t] = acc;
    }
    __syncthreads();

    float acc = b_r[t];
    #pragma unroll 8
    for (int d = 0; d < DDIM; d++)
        acc += h0[d] * W_r[d * HD + t];
    g_xr0[t] = acc;
}

// ---------------------------------------------------------------------------
// K1: compact edges with dst == 0.
// edge_index is (2, E) row-major: src at [0..E), dst at [E..2E).
// ---------------------------------------------------------------------------
__global__ void k_scan(const int* __restrict__ edge_index, int E) {
    int i = blockIdx.x * blockDim.x + threadIdx.x;
    int stride = gridDim.x * blockDim.x;
    for (; i < E; i += stride) {
        if (edge_index[E + i] == 0) {
            int pos = atomicAdd(&g_cnt, 1);
            if (pos < CAP) g_src[pos] = edge_index[i];
        }
    }
}

// ---------------------------------------------------------------------------
// K2: per relevant edge (src s): h_s, xl = h_s@W_l+b_l, logit per head,
//     p = exp(logit) (max-shift dropped: softmax is shift-invariant and
//     logits here are O(1)), accumulate num += p*xl, den += p.
// grid-stride over edges, 512 threads/block.
// ---------------------------------------------------------------------------
__global__ void k_edges(const float* __restrict__ nf,
                        const float* __restrict__ W_enc,
                        const float* __restrict__ b_enc,
                        const float* __restrict__ W_l,
                        const float* __restrict__ b_l,
                        const float* __restrict__ att) {
    __shared__ float hs[DDIM];
    __shared__ float red[16];
    __shared__ float psh[HEADS];

    int t = threadIdx.x;
    int head = t >> 7;          // 128 threads per head
    int warp = t >> 5;
    int lane = t & 31;

    int cnt = g_cnt;
    if (cnt > CAP) cnt = CAP;

    for (int e = blockIdx.x; e < cnt; e += gridDim.x) {
        int s = g_src[e];

        if (t < DDIM) {
            float acc = b_enc[t];
            const float* row = nf + (size_t)s * F_IN;
            #pragma unroll
            for (int k = 0; k < F_IN; k++)
                acc += row[k] * W_enc[k * DDIM + t];
            hs[t] = fmaxf(acc, 0.0f);
        }
        __syncthreads();

        float xl = b_l[t];
        #pragma unroll 8
        for (int d = 0; d < DDIM; d++)
            xl += hs[d] * W_l[d * HD + t];

        float xs = xl + g_xr0[t];
        float lr = xs >= 0.0f ? xs : 0.2f * xs;   // leaky_relu(., 0.2)
        float v = lr * att[t];                    // att is [4,128] row-major == att[t]

        // reduce 128 threads per head: warp shuffle then 4-warp combine
        #pragma unroll
        for (int off = 16; off; off >>= 1)
            v += __shfl_xor_sync(0xffffffffu, v, off);
        if (lane == 0) red[warp] = v;
        __syncthreads();

        if (t < HEADS) {
            float logit = red[4*t] + red[4*t+1] + red[4*t+2] + red[4*t+3];
            float p = __expf(logit);
            psh[t] = p;
            atomicAdd(&g_den[t], p);
        }
        __syncthreads();

        float p = psh[head];
        atomicAdd(&g_num[t], p * xl);
        __syncthreads();   // protect hs/red/psh reuse next iteration
    }
}

// ---------------------------------------------------------------------------
// K3: gat0 = mean_h(num[h]/den[h]) + gat_bias; GRU cell; write (1,128).
// 1 block x 512 threads.
// ---------------------------------------------------------------------------
__global__ void k_final(const float* __restrict__ hidden,
                        const float* __restrict__ gat_bias,
                        const float* __restrict__ W_ih,
                        const float* __restrict__ W_hh,
                        const float* __restrict__ b_ih,
                        const float* __restrict__ b_hh,
                        float* __restrict__ out) {
    __shared__ float gat[DDIM];
    __shared__ float gi[RNN3];
    __shared__ float gh[RNN3];
    int t = threadIdx.x;

    if (t < DDIM) {
        float s = 0.0f;
        #pragma unroll
        for (int h = 0; h < HEADS; h++)
            s += g_num[h * DDIM + t] / fmaxf(g_den[h], 1e-16f);
        gat[t] = 0.25f * s + gat_bias[t];
    }
    __syncthreads();

    if (t < RNN3) {
        float a = b_ih[t];
        float b = b_hh[t];
        const float* wi = W_ih + (size_t)t * DDIM;
        const float* wh = W_hh + (size_t)t * DDIM;
        #pragma unroll 8
        for (int c = 0; c < DDIM; c++) {
            a += gat[c]    * wi[c];
            b += hidden[c] * wh[c];
        }
        gi[t] = a;
        gh[t] = b;
    }
    __syncthreads();

    if (t < DDIM) {
        float r  = 1.0f / (1.0f + expf(-(gi[t]        + gh[t])));
        float z  = 1.0f / (1.0f + expf(-(gi[DDIM+t]   + gh[DDIM+t])));
        float ng = tanhf(gi[2*DDIM+t] + r * gh[2*DDIM+t]);
        out[t] = (1.0f - z) * ng + z * hidden[t];
    }
}

// ---------------------------------------------------------------------------
// Inputs (metadata order):
//  0 node_features (N,32) f32      8 att (4,128) f32
//  1 hidden_state (1,128) f32      9 gat_bias (128) f32
//  2 W_enc (32,128) f32           10 W_ih (384,128) f32
//  3 b_enc (128) f32              11 W_hh (384,128) f32
//  4 W_l (128,512) f32            12 b_ih (384) f32
//  5 b_l (512) f32                13 b_hh (384) f32
//  6 W_r (128,512) f32            14 edge_index (2,E) i32
//  7 b_r (512) f32
// ---------------------------------------------------------------------------
extern "C" void kernel_launch(void* const* d_in, const int* in_sizes, int n_in,
                              void* d_out, int out_size) {
    const float* nf       = (const float*)d_in[0];
    const float* hidden   = (const float*)d_in[1];
    const float* W_enc    = (const float*)d_in[2];
    const float* b_enc    = (const float*)d_in[3];
    const float* W_l      = (const float*)d_in[4];
    const float* b_l      = (const float*)d_in[5];
    const float* W_r      = (const float*)d_in[6];
    const float* b_r      = (const float*)d_in[7];
    const float* att      = (const float*)d_in[8];
    const float* gat_bias = (const float*)d_in[9];
    const float* W_ih     = (const float*)d_in[10];
    const float* W_hh     = (const float*)d_in[11];
    const float* b_ih     = (const float*)d_in[12];
    const float* b_hh     = (const float*)d_in[13];
    const int*   ei       = (const int*)d_in[14];
    float* out = (float*)d_out;

    int E = in_sizes[14] / 2;

    k_init<<<1, 512>>>(nf, W_enc, b_enc, W_r, b_r);

    int scan_blocks = (E + 255) / 256;
    if (scan_blocks > 1184) scan_blocks = 1184;   // 8 waves-ish grid-stride
    k_scan<<<scan_blocks, 256>>>(ei, E);

    k_edges<<<128, 512>>>(nf, W_enc, b_enc, W_l, b_l, att);

    k_final<<<1, 512>>>(hidden, gat_bias, W_ih, W_hh, b_ih, b_hh, out);
}

// round 2
// speedup vs baseline: 1.8834x; 1.8834x over previous
#include <cuda_runtime.h>
#include <math.h>

// Problem constants (fixed by the dataset)
#define F_IN   32
#define DDIM   128
#define HEADS  4
#define HD     (HEADS * DDIM)   // 512
#define RNN3   384              // 3 * RNN_H
#define CAP    330000           // >= E + 1 (E = 320000)

// Scratch (allocation-free rule: __device__ globals)
__device__ int   g_src[CAP];
__device__ int   g_cnt;
__device__ float g_xr0[HD];
__device__ float g_num[HD];
__device__ float g_den[HEADS];

// ---------------------------------------------------------------------------
// K0: init accumulators, seed self-loop edge (src=0,dst=0), compute
//     h0 = relu(nf[0] @ W_enc + b_enc) and xr0 = h0 @ W_r + b_r.
// 1 block x 512 threads. (W_r access is coalesced: thread t reads W_r[d*512+t].)
// ---------------------------------------------------------------------------
__global__ void k_init(const float* __restrict__ nf,
                       const float* __restrict__ W_enc,
                       const float* __restrict__ b_enc,
                       const float* __restrict__ W_r,
                       const float* __restrict__ b_r) {
    __shared__ float h0[DDIM];
    int t = threadIdx.x;

    g_num[t] = 0.0f;
    if (t < HEADS) g_den[t] = 0.0f;
    if (t == 0) { g_cnt = 1; g_src[0] = 0; }  // self-loop of node 0

    if (t < DDIM) {
        float acc = b_enc[t];
        #pragma unroll
        for (int k = 0; k < F_IN; k++)
            acc += nf[k] * W_enc[k * DDIM + t];
        h0[t] = fmaxf(acc, 0.0f);
    }
    __syncthreads();

    float acc = b_r[t];
    #pragma unroll 8
    for (int d = 0; d < DDIM; d++)
        acc += h0[d] * W_r[d * HD + t];
    g_xr0[t] = acc;
}

// ---------------------------------------------------------------------------
// K1: compact edges with dst == 0.  dst half read as int4 (4x fewer LDGs).
// edge_index is (2, E) row-major: src at [0..E), dst at [E..2E).
// ---------------------------------------------------------------------------
__global__ void k_scan(const int* __restrict__ edge_index, int E) {
    const int4* dst4 = (const int4*)(edge_index + E);
    int n4 = E >> 2;
    int i = blockIdx.x * blockDim.x + threadIdx.x;
    int stride = gridDim.x * blockDim.x;
    for (; i < n4; i += stride) {
        int4 v = dst4[i];
        if (v.x == 0) { int p = atomicAdd(&g_cnt, 1); if (p < CAP) g_src[p] = edge_index[4*i+0]; }
        if (v.y == 0) { int p = atomicAdd(&g_cnt, 1); if (p < CAP) g_src[p] = edge_index[4*i+1]; }
        if (v.z == 0) { int p = atomicAdd(&g_cnt, 1); if (p < CAP) g_src[p] = edge_index[4*i+2]; }
        if (v.w == 0) { int p = atomicAdd(&g_cnt, 1); if (p < CAP) g_src[p] = edge_index[4*i+3]; }
    }
    // tail (E not multiple of 4)
    int tail = n4 * 4 + blockIdx.x * blockDim.x + threadIdx.x;
    if (tail < E && edge_index[E + tail] == 0) {
        int p = atomicAdd(&g_cnt, 1);
        if (p < CAP) g_src[p] = edge_index[tail];
    }
}

// ---------------------------------------------------------------------------
// K2: per relevant edge (src s): h_s, xl = h_s@W_l+b_l, logit per head,
//     p = exp(logit) (max-shift dropped: softmax is shift-invariant and
//     logits here are O(1)), accumulate num += p*xl, den += p.
// grid-stride over edges, 512 threads/block. W_l access coalesced.
// ---------------------------------------------------------------------------
__global__ void k_edges(const float* __restrict__ nf,
                        const float* __restrict__ W_enc,
                        const float* __restrict__ b_enc,
                        const float* __restrict__ W_l,
                        const float* __restrict__ b_l,
                        const float* __restrict__ att) {
    __shared__ float hs[DDIM];
    __shared__ float red[16];
    __shared__ float psh[HEADS];

    int t = threadIdx.x;
    int head = t >> 7;          // 128 threads per head
    int warp = t >> 5;
    int lane = t & 31;

    int cnt = g_cnt;
    if (cnt > CAP) cnt = CAP;

    for (int e = blockIdx.x; e < cnt; e += gridDim.x) {
        int s = g_src[e];

        if (t < DDIM) {
            float acc = b_enc[t];
            const float* row = nf + (size_t)s * F_IN;
            #pragma unroll
            for (int k = 0; k < F_IN; k++)
                acc += row[k] * W_enc[k * DDIM + t];
            hs[t] = fmaxf(acc, 0.0f);
        }
        __syncthreads();

        float xl = b_l[t];
        #pragma unroll 8
        for (int d = 0; d < DDIM; d++)
            xl += hs[d] * W_l[d * HD + t];

        float xs = xl + g_xr0[t];
        float lr = xs >= 0.0f ? xs : 0.2f * xs;   // leaky_relu(., 0.2)
        float v = lr * att[t];                    // att is [4,128] row-major == att[t]

        #pragma unroll
        for (int off = 16; off; off >>= 1)
            v += __shfl_xor_sync(0xffffffffu, v, off);
        if (lane == 0) red[warp] = v;
        __syncthreads();

        if (t < HEADS) {
            float logit = red[4*t] + red[4*t+1] + red[4*t+2] + red[4*t+3];
            float p = __expf(logit);
            psh[t] = p;
            atomicAdd(&g_den[t], p);
        }
        __syncthreads();

        float p = psh[head];
        atomicAdd(&g_num[t], p * xl);
        __syncthreads();   // protect hs/red/psh reuse next iteration
    }
}

// ---------------------------------------------------------------------------
// K3: gat0 = mean_h(num[h]/den[h]) + gat_bias; GRU cell; write (1,128).
// 1 block x 512 threads. WARP-COOPERATIVE matvec: one warp per output row,
// lanes load float4 of consecutive W (coalesced: 4 wavefronts/row), 4-row ILP
// to pipeline the shuffle reduction.
// ---------------------------------------------------------------------------
__global__ void k_final(const float* __restrict__ hidden,
                        const float* __restrict__ gat_bias,
                        const float* __restrict__ W_ih,
                        const float* __restrict__ W_hh,
                        const float* __restrict__ b_ih,
                        const float* __restrict__ b_hh,
                        float* __restrict__ out) {
    __shared__ float gat[DDIM];
    __shared__ float hid[DDIM];
    __shared__ float gi[RNN3];
    __shared__ float gh[RNN3];
    int t = threadIdx.x;
    int warp = t >> 5, lane = t & 31;

    if (t < DDIM) {
        float s = 0.0f;
        #pragma unroll
        for (int h = 0; h < HEADS; h++)
            s += g_num[h * DDIM + t] / fmaxf(g_den[h], 1e-16f);
        gat[t] = 0.25f * s + gat_bias[t];
        hid[t] = hidden[t];
    }
    __syncthreads();

    // Warps 0..7 -> gi rows (W_ih, gat); warps 8..15 -> gh rows (W_hh, hid).
    // Each warp owns 48 contiguous rows.
    {
        const bool ih = (warp < 8);
        const float* W  = ih ? W_ih : W_hh;
        const float* xv = ih ? gat  : hid;
        const float* bv = ih ? b_ih : b_hh;
        float*       ov = ih ? gi   : gh;
        int base = (warp & 7) * 48;

        float x0 = xv[lane * 4 + 0];
        float x1 = xv[lane * 4 + 1];
        float x2 = xv[lane * 4 + 2];
        float x3 = xv[lane * 4 + 3];

        for (int i = 0; i < 48; i += 4) {
            float acc[4];
            #pragma unroll
            for (int j = 0; j < 4; j++) {
                const float4 wv = *(const float4*)(W + (size_t)(base + i + j) * DDIM + lane * 4);
                acc[j] = wv.x * x0 + wv.y * x1 + wv.z * x2 + wv.w * x3;
            }
            #pragma unroll
            for (int off = 16; off; off >>= 1) {
                #pragma unroll
                for (int j = 0; j < 4; j++)
                    acc[j] += __shfl_xor_sync(0xffffffffu, acc[j], off);
            }
            if (lane == 0) {
                #pragma unroll
                for (int j = 0; j < 4; j++)
                    ov[base + i + j] = acc[j] + bv[base + i + j];
            }
        }
    }
    __syncthreads();

    if (t < DDIM) {
        float r  = 1.0f / (1.0f + expf(-(gi[t]        + gh[t])));
        float z  = 1.0f / (1.0f + expf(-(gi[DDIM+t]   + gh[DDIM+t])));
        float ng = tanhf(gi[2*DDIM+t] + r * gh[2*DDIM+t]);
        out[t] = (1.0f - z) * ng + z * hid[t];
    }
}

// ---------------------------------------------------------------------------
// Inputs (metadata order):
//  0 node_features (N,32) f32      8 att (4,128) f32
//  1 hidden_state (1,128) f32      9 gat_bias (128) f32
//  2 W_enc (32,128) f32           10 W_ih (384,128) f32
//  3 b_enc (128) f32              11 W_hh (384,128) f32
//  4 W_l (128,512) f32            12 b_ih (384) f32
//  5 b_l (512) f32                13 b_hh (384) f32
//  6 W_r (128,512) f32            14 edge_index (2,E) i32
//  7 b_r (512) f32
// ---------------------------------------------------------------------------
extern "C" void kernel_launch(void* const* d_in, const int* in_sizes, int n_in,
                              void* d_out, int out_size) {
    const float* nf       = (const float*)d_in[0];
    const float* hidden   = (const float*)d_in[1];
    const float* W_enc    = (const float*)d_in[2];
    const float* b_enc    = (const float*)d_in[3];
    const float* W_l      = (const float*)d_in[4];
    const float* b_l      = (const float*)d_in[5];
    const float* W_r      = (const float*)d_in[6];
    const float* b_r      = (const float*)d_in[7];
    const float* att      = (const float*)d_in[8];
    const float* gat_bias = (const float*)d_in[9];
    const float* W_ih     = (const float*)d_in[10];
    const float* W_hh     = (const float*)d_in[11];
    const float* b_ih     = (const float*)d_in[12];
    const float* b_hh     = (const float*)d_in[13];
    const int*   ei       = (const int*)d_in[14];
    float* out = (float*)d_out;

    int E = in_sizes[14] / 2;

    k_init<<<1, 512>>>(nf, W_enc, b_enc, W_r, b_r);

    int n4 = E >> 2;
    int scan_blocks = (n4 + 255) / 256;
    if (scan_blocks > 592) scan_blocks = 592;
    k_scan<<<scan_blocks, 256>>>(ei, E);

    k_edges<<<64, 512>>>(nf, W_enc, b_enc, W_l, b_l, att);

    k_final<<<1, 512>>>(hidden, gat_bias, W_ih, W_hh, b_ih, b_hh, out);
}

// round 3
// speedup vs baseline: 2.8692x; 1.5234x over previous
#include <cuda_runtime.h>
#include <math.h>

// Problem constants (fixed by the dataset)
#define F_IN   32
#define DDIM   128
#define HEADS  4
#define HD     (HEADS * DDIM)   // 512
#define RNN3   384              // 3 * RNN_H
#define NBLK   148              // one block per SM
#define NTHR   512
#define LCAP   2304             // >= worst-case hits per stripe (541*4 + tail + loop)

// Persistent scratch (allocation-free rule). Zero at module load; the finale
// block re-zeroes them every launch so graph replays stay correct.
__device__ float g_num[HD];
__device__ float g_den[HEADS];
__device__ int   g_done;
__device__ float g_sink;

__global__ void __launch_bounds__(NTHR, 1) fused_stgat(
    const float* __restrict__ nf,     const float* __restrict__ hidden,
    const float* __restrict__ W_enc,  const float* __restrict__ b_enc,
    const float* __restrict__ W_l,    const float* __restrict__ b_l,
    const float* __restrict__ W_r,    const float* __restrict__ b_r,
    const float* __restrict__ att,    const float* __restrict__ gat_bias,
    const float* __restrict__ W_ih,   const float* __restrict__ W_hh,
    const float* __restrict__ b_ih,   const float* __restrict__ b_hh,
    const int*   __restrict__ ei,     int E,
    float* __restrict__ out)
{
    __shared__ int   ls[LCAP];
    __shared__ int   lcnt;
    __shared__ float xr0[HD];
    __shared__ float hs[DDIM];
    __shared__ float red[16];
    __shared__ float psh[HEADS];
    __shared__ int   is_last;
    __shared__ float gat[DDIM];
    __shared__ float hid[DDIM];
    __shared__ float gi[RNN3];
    __shared__ float gh[RNN3];

    const int t = threadIdx.x, b = blockIdx.x;
    const int warp = t >> 5, lane = t & 31;

    if (t == 0) lcnt = 0;
    __syncthreads();

    // ---------- Phase 1: scan my stripe of dst for dst == 0 ----------
    const int n4 = E >> 2;
    const int chunk = (n4 + NBLK - 1) / NBLK;
    const int lo = b * chunk;
    const int hi = min(n4, lo + chunk);
    const int4* dst4 = (const int4*)(ei + E);
    for (int i = lo + t; i < hi; i += NTHR) {
        int4 v = dst4[i];
        if (v.x == 0) ls[atomicAdd(&lcnt, 1)] = ei[4*i+0];
        if (v.y == 0) ls[atomicAdd(&lcnt, 1)] = ei[4*i+1];
        if (v.z == 0) ls[atomicAdd(&lcnt, 1)] = ei[4*i+2];
        if (v.w == 0) ls[atomicAdd(&lcnt, 1)] = ei[4*i+3];
    }
    if (b == 0) {
        for (int i = 4*n4 + t; i < E; i += NTHR)        // tail if E % 4 != 0
            if (ei[E + i] == 0) ls[atomicAdd(&lcnt, 1)] = ei[i];
        if (t == 0) ls[atomicAdd(&lcnt, 1)] = 0;        // self-loop of node 0
    }

    // L2 prefetch of GRU weights in parallel across all blocks (helps the
    // cold-cache case; harmless when warm). 148*512 threads cover 49152 floats.
    {
        int idx = b * NTHR + t;
        float s = 0.f;
        if (idx < RNN3 * DDIM) s = W_ih[idx] + W_hh[idx];
        if (s == 1.2345e-30f) g_sink = s;   // never true; defeats DCE
    }
    __syncthreads();

    // ---------- Phase 2: process locally-found edges ----------
    const int cnt = min(lcnt, LCAP);
    if (cnt > 0) {
        // h0 = relu(nf[0] @ W_enc + b_enc) ; xr0 = h0 @ W_r + b_r
        if (t < DDIM) {
            float a = b_enc[t];
            #pragma unroll
            for (int k = 0; k < F_IN; k++) a += nf[k] * W_enc[k*DDIM + t];
            hs[t] = fmaxf(a, 0.f);
        }
        __syncthreads();
        {
            float a = b_r[t];
            #pragma unroll 8
            for (int d = 0; d < DDIM; d++) a += hs[d] * W_r[d*HD + t];
            xr0[t] = a;
        }
        __syncthreads();

        for (int e = 0; e < cnt; e++) {
            const int s = ls[e];
            if (t < DDIM) {
                float a = b_enc[t];
                const float* row = nf + (size_t)s * F_IN;
                #pragma unroll
                for (int k = 0; k < F_IN; k++) a += row[k] * W_enc[k*DDIM + t];
                hs[t] = fmaxf(a, 0.f);
            }
            __syncthreads();

            float xl = b_l[t];
            #pragma unroll 8
            for (int d = 0; d < DDIM; d++) xl += hs[d] * W_l[d*HD + t];

            float xs = xl + xr0[t];
            float lr = xs >= 0.f ? xs : 0.2f * xs;       // leaky_relu 0.2
            float v = lr * att[t];                       // att [4,128] row-major
            #pragma unroll
            for (int off = 16; off; off >>= 1)
                v += __shfl_xor_sync(0xffffffffu, v, off);
            if (lane == 0) red[warp] = v;
            __syncthreads();

            if (t < HEADS) {
                // softmax shift dropped (shift-invariant, logits O(1))
                float p = __expf(red[4*t] + red[4*t+1] + red[4*t+2] + red[4*t+3]);
                psh[t] = p;
                atomicAdd(&g_den[t], p);
            }
            __syncthreads();

            atomicAdd(&g_num[t], psh[t >> 7] * xl);
            __syncthreads();   // protect hs/red/psh reuse
        }
    }

    // ---------- Phase 3: last-arriving block does the GRU finale ----------
    __threadfence();
    if (t == 0) {
        int old = atomicAdd(&g_done, 1);
        is_last = (old == NBLK - 1);
    }
    __syncthreads();
    if (!is_last) return;

    __threadfence();   // acquire: all blocks' g_num/g_den atomics visible

    if (t < DDIM) {
        float s = 0.f;
        #pragma unroll
        for (int h = 0; h < HEADS; h++)
            s += g_num[h*DDIM + t] / fmaxf(g_den[h], 1e-16f);
        gat[t] = 0.25f * s + gat_bias[t];
        hid[t] = hidden[t];
    }
    __syncthreads();

    // reset persistent state for the next graph replay
    g_num[t] = 0.f;
    if (t < HEADS) g_den[t] = 0.f;
    if (t == 0) g_done = 0;

    // Warp-cooperative GRU matvecs: warps 0..7 -> gi (W_ih, gat),
    // warps 8..15 -> gh (W_hh, hid). 48 rows/warp, float4 loads, 4-row ILP.
    {
        const bool ih_side = (warp < 8);
        const float* W  = ih_side ? W_ih : W_hh;
        const float* xv = ih_side ? gat  : hid;
        const float* bv = ih_side ? b_ih : b_hh;
        float*       ov = ih_side ? gi   : gh;
        const int base = (warp & 7) * 48;

        const float x0 = xv[lane*4 + 0];
        const float x1 = xv[lane*4 + 1];
        const float x2 = xv[lane*4 + 2];
        const float x3 = xv[lane*4 + 3];

        for (int i = 0; i < 48; i += 4) {
            float acc[4];
            #pragma unroll
            for (int j = 0; j < 4; j++) {
                const float4 wv = *(const float4*)(W + (size_t)(base+i+j)*DDIM + lane*4);
                acc[j] = wv.x*x0 + wv.y*x1 + wv.z*x2 + wv.w*x3;
            }
            #pragma unroll
            for (int off = 16; off; off >>= 1) {
                #pragma unroll
                for (int j = 0; j < 4; j++)
                    acc[j] += __shfl_xor_sync(0xffffffffu, acc[j], off);
            }
            if (lane == 0) {
                #pragma unroll
                for (int j = 0; j < 4; j++)
                    ov[base+i+j] = acc[j] + bv[base+i+j];
            }
        }
    }
    __syncthreads();

    if (t < DDIM) {
        float r  = 1.f / (1.f + expf(-(gi[t]        + gh[t])));
        float z  = 1.f / (1.f + expf(-(gi[DDIM+t]   + gh[DDIM+t])));
        float ng = tanhf(gi[2*DDIM+t] + r * gh[2*DDIM+t]);
        out[t] = (1.f - z) * ng + z * hid[t];
    }
}

// ---------------------------------------------------------------------------
// Inputs (metadata order):
//  0 node_features (N,32) f32      8 att (4,128) f32
//  1 hidden_state (1,128) f32      9 gat_bias (128) f32
//  2 W_enc (32,128) f32           10 W_ih (384,128) f32
//  3 b_enc (128) f32              11 W_hh (384,128) f32
//  4 W_l (128,512) f32            12 b_ih (384) f32
//  5 b_l (512) f32                13 b_hh (384) f32
//  6 W_r (128,512) f32            14 edge_index (2,E) i32
//  7 b_r (512) f32
// ---------------------------------------------------------------------------
extern "C" void kernel_launch(void* const* d_in, const int* in_sizes, int n_in,
                              void* d_out, int out_size) {
    const float* nf       = (const float*)d_in[0];
    const float* hidden   = (const float*)d_in[1];
    const float* W_enc    = (const float*)d_in[2];
    const float* b_enc    = (const float*)d_in[3];
    const float* W_l      = (const float*)d_in[4];
    const float* b_l      = (const float*)d_in[5];
    const float* W_r      = (const float*)d_in[6];
    const float* b_r      = (const float*)d_in[7];
    const float* att      = (const float*)d_in[8];
    const float* gat_bias = (const float*)d_in[9];
    const float* W_ih     = (const float*)d_in[10];
    const float* W_hh     = (const float*)d_in[11];
    const float* b_ih     = (const float*)d_in[12];
    const float* b_hh     = (const float*)d_in[13];
    const int*   ei       = (const int*)d_in[14];
    float* out = (float*)d_out;

    int E = in_sizes[14] / 2;

    fused_stgat<<<NBLK, NTHR>>>(nf, hidden, W_enc, b_enc, W_l, b_l, W_r, b_r,
                                att, gat_bias, W_ih, W_hh, b_ih, b_hh, ei, E, out);
}

// round 4
// speedup vs baseline: 4.1486x; 1.4459x over previous
#include <cuda_runtime.h>
#include <math.h>

#define F_IN   32
#define DDIM   128
#define HEADS  4
#define HD     (HEADS * DDIM)   // 512
#define RNN3   384
#define NBLK   148
#define NTHR   512
#define NSCAN  146               // blocks 0..145 scan; 146 -> gh; 147 -> h0/xr0
#define LCAP   4096              // local per-block hit capacity

// Persistent scratch (allocation-free rule). Finale resets everything it
// consumes so graph replays stay correct (launches are stream-serialized).
__device__ float g_num[HD];
__device__ float g_den[HEADS];
__device__ int   g_done;
__device__ volatile int g_xr0_flag;
__device__ float g_xr0[HD];
__device__ float g_gh[RNN3];
__device__ float g_sink;

__global__ void __launch_bounds__(NTHR, 1) fused_stgat(
    const float* __restrict__ nf,     const float* __restrict__ hidden,
    const float* __restrict__ W_enc,  const float* __restrict__ b_enc,
    const float* __restrict__ W_l,    const float* __restrict__ b_l,
    const float* __restrict__ W_r,    const float* __restrict__ b_r,
    const float* __restrict__ att,    const float* __restrict__ gat_bias,
    const float* __restrict__ W_ih,   const float* __restrict__ W_hh,
    const float* __restrict__ b_ih,   const float* __restrict__ b_hh,
    const int*   __restrict__ ei,     int E,
    float* __restrict__ out)
{
    __shared__ int   ls[LCAP];
    __shared__ int   lcnt;
    __shared__ float hs[DDIM];
    __shared__ float red[16];
    __shared__ float psh[HEADS];
    __shared__ int   is_last;
    __shared__ float gat[DDIM];
    __shared__ float gi[RNN3];

    const int t = threadIdx.x, b = blockIdx.x;
    const int warp = t >> 5, lane = t & 31;

    if (t == 0) lcnt = 0;
    __syncthreads();

    const int n4 = E >> 2;

    if (b == NBLK - 1) {
        // ---------- Producer block: h0 = relu(nf[0]@W_enc+b_enc), xr0 = h0@W_r+b_r
        if (t < DDIM) {
            float a = b_enc[t];
            #pragma unroll
            for (int k = 0; k < F_IN; k++) a += nf[k] * W_enc[k*DDIM + t];
            hs[t] = fmaxf(a, 0.f);
        }
        __syncthreads();
        {
            float acc = b_r[t];
            #pragma unroll
            for (int d0 = 0; d0 < DDIM; d0 += 32) {
                float w[32];
                #pragma unroll
                for (int j = 0; j < 32; j++) w[j] = W_r[(d0+j)*HD + t];
                #pragma unroll
                for (int j = 0; j < 32; j++) acc += hs[d0+j] * w[j];
            }
            g_xr0[t] = acc;
        }
        __threadfence();
        __syncthreads();
        if (t == 0) g_xr0_flag = 1;
    } else if (b == NBLK - 2) {
        // ---------- gh = hidden @ W_hh.T + b_hh (input-only; finale reads after barrier)
        // 16 warps x 24 rows, float4 coalesced, 4-row ILP.
        __shared__ float hid[DDIM];
        if (t < DDIM) hid[t] = hidden[t];
        __syncthreads();
        const int base = warp * 24;
        const float x0 = hid[lane*4+0], x1 = hid[lane*4+1];
        const float x2 = hid[lane*4+2], x3 = hid[lane*4+3];
        for (int i = 0; i < 24; i += 4) {
            float acc[4];
            #pragma unroll
            for (int j = 0; j < 4; j++) {
                const float4 wv = *(const float4*)(W_hh + (size_t)(base+i+j)*DDIM + lane*4);
                acc[j] = wv.x*x0 + wv.y*x1 + wv.z*x2 + wv.w*x3;
            }
            #pragma unroll
            for (int off = 16; off; off >>= 1)
                #pragma unroll
                for (int j = 0; j < 4; j++)
                    acc[j] += __shfl_xor_sync(0xffffffffu, acc[j], off);
            if (lane == 0)
                #pragma unroll
                for (int j = 0; j < 4; j++)
                    g_gh[base+i+j] = acc[j] + b_hh[base+i+j];
        }
        // L2 warm for W_ih (finale reads it) — spread over this block too
        float s = 0.f;
        for (int idx = t; idx < RNN3*DDIM; idx += NTHR*16) s += W_ih[idx];
        if (s == 1.2345e-30f) g_sink = s;
    } else {
        // ---------- Scan my stripe of dst for dst == 0 ----------
        const int chunk = (n4 + NSCAN - 1) / NSCAN;
        const int lo = b * chunk;
        const int hi = min(n4, lo + chunk);
        const int4* dst4 = (const int4*)(ei + E);
        for (int i = lo + t; i < hi; i += NTHR) {
            int4 v = dst4[i];
            if (v.x == 0) ls[atomicAdd(&lcnt, 1)] = ei[4*i+0];
            if (v.y == 0) ls[atomicAdd(&lcnt, 1)] = ei[4*i+1];
            if (v.z == 0) ls[atomicAdd(&lcnt, 1)] = ei[4*i+2];
            if (v.w == 0) ls[atomicAdd(&lcnt, 1)] = ei[4*i+3];
        }
        if (b == 0) {
            for (int i = 4*n4 + t; i < E; i += NTHR)       // tail if E%4
                if (ei[E + i] == 0) ls[atomicAdd(&lcnt, 1)] = ei[i];
            if (t == 0) ls[atomicAdd(&lcnt, 1)] = 0;       // self-loop node 0
        }
        __syncthreads();

        // ---------- Process locally-found edges ----------
        const int cnt = min(lcnt, LCAP);
        if (cnt > 0) {
            // wait for xr0 (producer runs concurrently with scan; usually ready)
            if (t == 0) { while (g_xr0_flag == 0) {} }
            __syncthreads();
            __threadfence();
            const float myxr0 = g_xr0[t];

            for (int e = 0; e < cnt; e++) {
                const int s = ls[e];
                if (t < DDIM) {
                    float a = b_enc[t];
                    const float* row = nf + (size_t)s * F_IN;
                    #pragma unroll
                    for (int k = 0; k < F_IN; k++) a += row[k] * W_enc[k*DDIM + t];
                    hs[t] = fmaxf(a, 0.f);
                }
                __syncthreads();

                float xl = b_l[t];
                #pragma unroll
                for (int d0 = 0; d0 < DDIM; d0 += 32) {
                    float w[32];
                    #pragma unroll
                    for (int j = 0; j < 32; j++) w[j] = W_l[(d0+j)*HD + t];
                    #pragma unroll
                    for (int j = 0; j < 32; j++) xl += hs[d0+j] * w[j];
                }

                float xs = xl + myxr0;
                float lr = xs >= 0.f ? xs : 0.2f * xs;     // leaky_relu 0.2
                float v = lr * att[t];
                #pragma unroll
                for (int off = 16; off; off >>= 1)
                    v += __shfl_xor_sync(0xffffffffu, v, off);
                if (lane == 0) red[warp] = v;
                __syncthreads();

                if (t < HEADS) {
                    // softmax shift dropped (shift-invariant; logits O(1))
                    float p = __expf(red[4*t] + red[4*t+1] + red[4*t+2] + red[4*t+3]);
                    psh[t] = p;
                    atomicAdd(&g_den[t], p);
                }
                __syncthreads();

                atomicAdd(&g_num[t], psh[t >> 7] * xl);
                __syncthreads();
            }
        }
    }

    // ---------- Barrier: last-arriving block does the GRU finale ----------
    __threadfence();
    if (t == 0) is_last = (atomicAdd(&g_done, 1) == NBLK - 1);
    __syncthreads();
    if (!is_last) return;
    __threadfence();   // acquire all blocks' writes

    if (t < DDIM) {
        float s = 0.f;
        #pragma unroll
        for (int h = 0; h < HEADS; h++)
            s += g_num[h*DDIM + t] / fmaxf(g_den[h], 1e-16f);
        gat[t] = 0.25f * s + gat_bias[t];
    }
    __syncthreads();

    // reset persistent state for the next graph replay
    g_num[t] = 0.f;
    if (t < HEADS) g_den[t] = 0.f;
    if (t == 0) { g_done = 0; g_xr0_flag = 0; }

    // gi = gat @ W_ih.T + b_ih : 16 warps x 24 rows, float4, 4-row ILP
    {
        const int base = warp * 24;
        const float x0 = gat[lane*4+0], x1 = gat[lane*4+1];
        const float x2 = gat[lane*4+2], x3 = gat[lane*4+3];
        for (int i = 0; i < 24; i += 4) {
            float acc[4];
            #pragma unroll
            for (int j = 0; j < 4; j++) {
                const float4 wv = *(const float4*)(W_ih + (size_t)(base+i+j)*DDIM + lane*4);
                acc[j] = wv.x*x0 + wv.y*x1 + wv.z*x2 + wv.w*x3;
            }
            #pragma unroll
            for (int off = 16; off; off >>= 1)
                #pragma unroll
                for (int j = 0; j < 4; j++)
                    acc[j] += __shfl_xor_sync(0xffffffffu, acc[j], off);
            if (lane == 0)
                #pragma unroll
                for (int j = 0; j < 4; j++)
                    gi[base+i+j] = acc[j] + b_ih[base+i+j];
        }
    }
    __syncthreads();

    if (t < DDIM) {
        float r  = 1.f / (1.f + expf(-(gi[t]        + g_gh[t])));
        float z  = 1.f / (1.f + expf(-(gi[DDIM+t]   + g_gh[DDIM+t])));
        float ng = tanhf(gi[2*DDIM+t] + r * g_gh[2*DDIM+t]);
        out[t] = (1.f - z) * ng + z * hidden[t];
    }
}

extern "C" void kernel_launch(void* const* d_in, const int* in_sizes, int n_in,
                              void* d_out, int out_size) {
    const float* nf       = (const float*)d_in[0];
    const float* hidden   = (const float*)d_in[1];
    const float* W_enc    = (const float*)d_in[2];
    const float* b_enc    = (const float*)d_in[3];
    const float* W_l      = (const float*)d_in[4];
    const float* b_l      = (const float*)d_in[5];
    const float* W_r      = (const float*)d_in[6];
    const float* b_r      = (const float*)d_in[7];
    const float* att      = (const float*)d_in[8];
    const float* gat_bias = (const float*)d_in[9];
    const float* W_ih     = (const float*)d_in[10];
    const float* W_hh     = (const float*)d_in[11];
    const float* b_ih     = (const float*)d_in[12];
    const float* b_hh     = (const float*)d_in[13];
    const int*   ei       = (const int*)d_in[14];
    float* out = (float*)d_out;

    int E = in_sizes[14] / 2;

    fused_stgat<<<NBLK, NTHR>>>(nf, hidden, W_enc, b_enc, W_l, b_l, W_r, b_r,
                                att, gat_bias, W_ih, W_hh, b_ih, b_hh, ei, E, out);
}

// round 6
// speedup vs baseline: 4.7875x; 1.1540x over previous
#include <cuda_runtime.h>
#include <math.h>

#define F_IN   32
#define DDIM   128
#define HEADS  4
#define HD     512               // HEADS * DDIM
#define RNN3   384
#define NBLK   148
#define NTHR   512
#define NSCAN  146               // blocks 0..145 scan; 146 -> gh; 147 -> h0/xr0
#define LCAP   4096

// Persistent scratch (allocation-free rule). Finale resets all consumed state
// so graph replays stay correct (launches are stream-serialized).
__device__ float g_num[HD];
__device__ float g_den[HEADS];
__device__ int   g_done;
__device__ volatile int g_xr0_flag;
__device__ float g_xr0[HD];
__device__ float g_gh[RNN3];

__global__ void __launch_bounds__(NTHR, 1) fused_stgat(
    const float* __restrict__ nf,     const float* __restrict__ hidden,
    const float* __restrict__ W_enc,  const float* __restrict__ b_enc,
    const float* __restrict__ W_l,    const float* __restrict__ b_l,
    const float* __restrict__ W_r,    const float* __restrict__ b_r,
    const float* __restrict__ att,    const float* __restrict__ gat_bias,
    const float* __restrict__ W_ih,   const float* __restrict__ W_hh,
    const float* __restrict__ b_ih,   const float* __restrict__ b_hh,
    const int*   __restrict__ ei,     int E,
    float* __restrict__ out)
{
    __shared__ int   ls[LCAP];
    __shared__ int   lcnt;
    __shared__ __align__(16) float hs[DDIM];
    __shared__ __align__(16) float part[4 * HD];   // 4-way K-split partials
    __shared__ float red[16];
    __shared__ float psh[HEADS];
    __shared__ int   is_last;
    __shared__ float gat[DDIM];
    __shared__ float gi[RNN3];

    const int t = threadIdx.x, b = blockIdx.x;
    const int warp = t >> 5, lane = t & 31;
    const int grp = t >> 7, q = t & 127;   // 4 K-groups x 128 output-quads

    if (t == 0) lcnt = 0;
    __syncthreads();

    const int n4 = E >> 2;

    if (b == NBLK - 1) {
        // ---------- Producer: h0 = relu(nf[0]@W_enc+b_enc); xr0 = h0@W_r+b_r
        {   // hs partials: group grp covers k in [8*grp, 8*grp+8)
            float a = 0.f;
            #pragma unroll
            for (int k = 0; k < 8; k++)
                a += nf[grp*8 + k] * W_enc[(grp*8 + k)*DDIM + q];
            part[grp*DDIM + q] = a;
        }
        __syncthreads();
        if (t < DDIM)
            hs[t] = fmaxf(b_enc[t] + part[t] + part[DDIM+t] + part[2*DDIM+t] + part[3*DDIM+t], 0.f);
        __syncthreads();
        {   // xr0: float4, 4-way K split (grp covers d in [32*grp, 32*grp+32))
            float4 a = make_float4(0.f, 0.f, 0.f, 0.f);
            const float* Wb = W_r + (size_t)(grp*32)*HD + 4*q;
            #pragma unroll
            for (int j = 0; j < 32; j++) {
                const float4 wv = *(const float4*)(Wb + (size_t)j*HD);
                const float hv = hs[grp*32 + j];
                a.x += hv*wv.x; a.y += hv*wv.y; a.z += hv*wv.z; a.w += hv*wv.w;
            }
            *(float4*)(part + grp*HD + 4*q) = a;
        }
        __syncthreads();
        g_xr0[t] = b_r[t] + part[t] + part[HD+t] + part[2*HD+t] + part[3*HD+t];
        __threadfence();
        __syncthreads();
        if (t == 0) g_xr0_flag = 1;
    } else if (b == NBLK - 2) {
        // ---------- gh = hidden @ W_hh.T + b_hh (16 warps x 24 rows, float4)
        __shared__ float hid[DDIM];
        if (t < DDIM) hid[t] = hidden[t];
        __syncthreads();
        const int base = warp * 24;
        const float x0 = hid[lane*4+0], x1 = hid[lane*4+1];
        const float x2 = hid[lane*4+2], x3 = hid[lane*4+3];
        for (int i = 0; i < 24; i += 4) {
            float acc[4];
            #pragma unroll
            for (int j = 0; j < 4; j++) {
                const float4 wv = *(const float4*)(W_hh + (size_t)(base+i+j)*DDIM + lane*4);
                acc[j] = wv.x*x0 + wv.y*x1 + wv.z*x2 + wv.w*x3;
            }
            #pragma unroll
            for (int off = 16; off; off >>= 1)
                #pragma unroll
                for (int j = 0; j < 4; j++)
                    acc[j] += __shfl_xor_sync(0xffffffffu, acc[j], off);
            if (lane == 0)
                #pragma unroll
                for (int j = 0; j < 4; j++)
                    g_gh[base+i+j] = acc[j] + b_hh[base+i+j];
        }
    } else {
        // ---------- Scan my stripe of dst for dst == 0 ----------
        const int chunk = (n4 + NSCAN - 1) / NSCAN;
        const int lo = b * chunk;
        const int hi = min(n4, lo + chunk);
        const int4* dst4 = (const int4*)(ei + E);
        for (int i = lo + t; i < hi; i += NTHR) {
            int4 v = dst4[i];
            if (v.x == 0) ls[atomicAdd(&lcnt, 1)] = ei[4*i+0];
            if (v.y == 0) ls[atomicAdd(&lcnt, 1)] = ei[4*i+1];
            if (v.z == 0) ls[atomicAdd(&lcnt, 1)] = ei[4*i+2];
            if (v.w == 0) ls[atomicAdd(&lcnt, 1)] = ei[4*i+3];
        }
        if (b == 0) {
            for (int i = 4*n4 + t; i < E; i += NTHR)       // tail if E % 4
                if (ei[E + i] == 0) ls[atomicAdd(&lcnt, 1)] = ei[i];
            if (t == 0) ls[atomicAdd(&lcnt, 1)] = 0;       // self-loop node 0
        }
        __syncthreads();

        // ---------- Process locally-found edges ----------
        const int cnt = min(lcnt, LCAP);
        if (cnt > 0) {
            bool got = false;
            float myxr0 = 0.f;

            for (int e = 0; e < cnt; e++) {
                const int s = ls[e];
                {   // hs partials
                    const float* row = nf + (size_t)s * F_IN;
                    float a = 0.f;
                    #pragma unroll
                    for (int k = 0; k < 8; k++)
                        a += row[grp*8 + k] * W_enc[(grp*8 + k)*DDIM + q];
                    part[grp*DDIM + q] = a;
                }
                __syncthreads();
                if (t < DDIM)
                    hs[t] = fmaxf(b_enc[t] + part[t] + part[DDIM+t] + part[2*DDIM+t] + part[3*DDIM+t], 0.f);
                __syncthreads();

                {   // xl: float4 4-way K split
                    float4 a = make_float4(0.f, 0.f, 0.f, 0.f);
                    const float* Wb = W_l + (size_t)(grp*32)*HD + 4*q;
                    #pragma unroll
                    for (int j = 0; j < 32; j++) {
                        const float4 wv = *(const float4*)(Wb + (size_t)j*HD);
                        const float hv = hs[grp*32 + j];
                        a.x += hv*wv.x; a.y += hv*wv.y; a.z += hv*wv.z; a.w += hv*wv.w;
                    }
                    *(float4*)(part + grp*HD + 4*q) = a;
                }
                __syncthreads();
                const float xl = b_l[t] + part[t] + part[HD+t] + part[2*HD+t] + part[3*HD+t];

                if (!got) {   // xr0 only needed from here; producer overlapped
                    if (t == 0) { while (g_xr0_flag == 0) {} }
                    __syncthreads();
                    __threadfence();
                    myxr0 = g_xr0[t];
                    got = true;
                }

                const float xs = xl + myxr0;
                const float lr = xs >= 0.f ? xs : 0.2f * xs;   // leaky_relu 0.2
                float v = lr * att[t];                          // att [4,128] row-major
                #pragma unroll
                for (int off = 16; off; off >>= 1)
                    v += __shfl_xor_sync(0xffffffffu, v, off);
                if (lane == 0) red[warp] = v;
                __syncthreads();

                if (t < HEADS) {
                    // softmax shift dropped (shift-invariant; logits O(1))
                    float p = __expf(red[4*t] + red[4*t+1] + red[4*t+2] + red[4*t+3]);
                    psh[t] = p;
                    atomicAdd(&g_den[t], p);
                }
                __syncthreads();

                atomicAdd(&g_num[t], psh[t >> 7] * xl);
                __syncthreads();
            }
        }
    }

    // ---------- Barrier: last-arriving block does the GRU finale ----------
    __threadfence();
    if (t == 0) is_last = (atomicAdd(&g_done, 1) == NBLK - 1);
    __syncthreads();
    if (!is_last) return;
    __threadfence();   // acquire all blocks' writes

    if (t < DDIM) {
        float s = 0.f;
        #pragma unroll
        for (int h = 0; h < HEADS; h++)
            s += g_num[h*DDIM + t] / fmaxf(g_den[h], 1e-16f);
        gat[t] = 0.25f * s + gat_bias[t];
    }
    __syncthreads();

    // reset persistent state for the next graph replay
    g_num[t] = 0.f;
    if (t < HEADS) g_den[t] = 0.f;
    if (t == 0) { g_done = 0; g_xr0_flag = 0; }

    // gi = gat @ W_ih.T + b_ih : 16 warps x 24 rows, float4, 4-row ILP
    {
        const int base = warp * 24;
        const float x0 = gat[lane*4+0], x1 = gat[lane*4+1];
        const float x2 = gat[lane*4+2], x3 = gat[lane*4+3];
        for (int i = 0; i < 24; i += 4) {
            float acc[4];
            #pragma unroll
            for (int j = 0; j < 4; j++) {
                const float4 wv = *(const float4*)(W_ih + (size_t)(base+i+j)*DDIM + lane*4);
                acc[j] = wv.x*x0 + wv.y*x1 + wv.z*x2 + wv.w*x3;
            }
            #pragma unroll
            for (int off = 16; off; off >>= 1)
                #pragma unroll
                for (int j = 0; j < 4; j++)
                    acc[j] += __shfl_xor_sync(0xffffffffu, acc[j], off);
            if (lane == 0)
                #pragma unroll
                for (int j = 0; j < 4; j++)
                    gi[base+i+j] = acc[j] + b_ih[base+i+j];
        }
    }
    __syncthreads();

    if (t < DDIM) {
        float r  = 1.f / (1.f + expf(-(gi[t]        + g_gh[t])));
        float z  = 1.f / (1.f + expf(-(gi[DDIM+t]   + g_gh[DDIM+t])));
        float ng = tanhf(gi[2*DDIM+t] + r * g_gh[2*DDIM+t]);
        out[t] = (1.f - z) * ng + z * hidden[t];
    }
}

extern "C" void kernel_launch(void* const* d_in, const int* in_sizes, int n_in,
                              void* d_out, int out_size) {
    const float* nf       = (const float*)d_in[0];
    const float* hidden   = (const float*)d_in[1];
    const float* W_enc    = (const float*)d_in[2];
    const float* b_enc    = (const float*)d_in[3];
    const float* W_l      = (const float*)d_in[4];
    const float* b_l      = (const float*)d_in[5];
    const float* W_r      = (const float*)d_in[6];
    const float* b_r      = (const float*)d_in[7];
    const float* att      = (const float*)d_in[8];
    const float* gat_bias = (const float*)d_in[9];
    const float* W_ih     = (const float*)d_in[10];
    const float* W_hh     = (const float*)d_in[11];
    const float* b_ih     = (const float*)d_in[12];
    const float* b_hh     = (const float*)d_in[13];
    const int*   ei       = (const int*)d_in[14];
    float* out = (float*)d_out;

    int E = in_sizes[14] / 2;

    fused_stgat<<<NBLK, NTHR>>>(nf, hidden, W_enc, b_enc, W_l, b_l, W_r, b_r,
                                att, gat_bias, W_ih, W_hh, b_ih, b_hh, ei, E, out);
}